// round 1
// baseline (speedup 1.0000x reference)
#include <cuda_runtime.h>
#include <math.h>
#include <float.h>

#define BB 64
#define NN 32768
#define CC 2
#define KK 10

static __device__ __forceinline__ float sigmoidf_(float x) {
    return 1.0f / (1.0f + expf(-x));
}
static __device__ __forceinline__ float softplusf_(float x) {
    return fmaxf(x, 0.0f) + log1pf(expf(-fabsf(x)));
}

// scratch: per-column features (s, e, g0, g1)
__device__ float4 g_scratch[BB * NN];
// top-10 candidates per (batch, gt-row), sorted by (val, col) ascending
__device__ float g_cand_val[BB * KK * KK];
__device__ int   g_cand_col[BB * KK * KK];

// ---------------------------------------------------------------------------
// Kernel A: per-column sigmoids + class-L2 precompute
// ---------------------------------------------------------------------------
__global__ void precompute_kernel(const float* __restrict__ ps,
                                  const float* __restrict__ pe,
                                  const float* __restrict__ pcl) {
    int i = blockIdx.x * blockDim.x + threadIdx.x;
    if (i >= BB * NN) return;
    float s = sigmoidf_(ps[i]);
    float e = sigmoidf_(pe[i]);
    float2 l = reinterpret_cast<const float2*>(pcl)[i];
    float c0 = sigmoidf_(l.x);
    float c1 = sigmoidf_(l.y);
    float g0 = (c0 - 1.0f) * (c0 - 1.0f) + c1 * c1;  // class 0 target
    float g1 = c0 * c0 + (c1 - 1.0f) * (c1 - 1.0f);  // class 1 target
    g_scratch[i] = make_float4(s, e, g0, g1);
}

// ---------------------------------------------------------------------------
// Kernel B: per (b, k) top-10 (cost, col). One warp per row-task.
// ---------------------------------------------------------------------------
__global__ void topk_kernel(const float* __restrict__ gt) {
    int warp = (blockIdx.x * blockDim.x + threadIdx.x) >> 5;
    int lane = threadIdx.x & 31;
    if (warp >= BB * KK) return;
    int b = warp / KK, k = warp % KK;

    const float* g = gt + (size_t)(b * KK + k) * 3;
    float fs = g[0], fe = g[1], cl = g[2];
    bool present = !((fs != fs) || (fe != fe) || (cl != cl));
    int obase = (b * KK + k) * KK;
    if (!present) {
        // absent row: sentinel candidates (never valid; never beats a present row)
        if (lane < KK) { g_cand_val[obase + lane] = 1.0e6f; g_cand_col[obase + lane] = lane; }
        return;
    }
    int cli = (int)cl;
    cli = cli < 0 ? 0 : (cli > CC - 1 ? CC - 1 : cli);

    // per-lane sorted top-10 (ascending by (val, col); ascending col iteration
    // + strict-less insert preserves col tie order)
    float bv[KK]; int bc[KK];
#pragma unroll
    for (int j = 0; j < KK; j++) { bv[j] = FLT_MAX; bc[j] = 0x7fffffff; }

    const float4* sc = g_scratch + (size_t)b * NN;
    for (int col = lane; col < NN; col += 128) {
        float4 v0 = sc[col];
        float4 v1 = sc[col + 32];
        float4 v2 = sc[col + 64];
        float4 v3 = sc[col + 96];
#pragma unroll
        for (int q = 0; q < 4; q++) {
            float4 v = (q == 0) ? v0 : (q == 1) ? v1 : (q == 2) ? v2 : v3;
            int c = col + q * 32;
            float gg = (cli == 0) ? v.z : v.w;
            float ds = v.x - fs, de = v.y - fe;
            float cost = fmaf(ds, ds, fmaf(de, de, gg));
            if (cost < bv[KK - 1]) {
                bv[KK - 1] = cost; bc[KK - 1] = c;
#pragma unroll
                for (int j = KK - 1; j > 0; j--) {
                    bool sw = (bv[j] < bv[j - 1]);
                    if (sw) {
                        float tv = bv[j]; bv[j] = bv[j - 1]; bv[j - 1] = tv;
                        int tc = bc[j]; bc[j] = bc[j - 1]; bc[j - 1] = tc;
                    }
                }
            }
        }
    }

    // warp merge: 10 rounds of butterfly-min over each lane's list head
    int p = 0;
    for (int r = 0; r < KK; r++) {
        float v = FLT_MAX; int c = 0x7fffffff;
#pragma unroll
        for (int j = KK - 1; j >= 0; j--) {
            if (j >= p) { v = bv[j]; c = bc[j]; }  // ends at j == p (lane's head)
        }
        int src = lane;
#pragma unroll
        for (int off = 16; off > 0; off >>= 1) {
            float v2 = __shfl_xor_sync(0xffffffffu, v, off);
            int   c2 = __shfl_xor_sync(0xffffffffu, c, off);
            int   s2 = __shfl_xor_sync(0xffffffffu, src, off);
            if (v2 < v || (v2 == v && c2 < c)) { v = v2; c = c2; src = s2; }
        }
        if (lane == 0) { g_cand_val[obase + r] = v; g_cand_col[obase + r] = c; }
        if (lane == src) p++;
    }
}

// ---------------------------------------------------------------------------
// Kernel C: greedy match on candidate lists + exact losses + final scalar
// ---------------------------------------------------------------------------
__global__ void match_kernel(const float* __restrict__ ps,
                             const float* __restrict__ pe,
                             const float* __restrict__ pcl,
                             const float* __restrict__ pcf,
                             const float* __restrict__ gt,
                             float* __restrict__ out) {
    int b = threadIdx.x;
    float part = 0.0f, m = 0.0f;
    if (b < BB) {
        float fs[KK], fe[KK]; int cli[KK]; bool pres[KK];
        for (int k = 0; k < KK; k++) {
            const float* g = gt + (size_t)(b * KK + k) * 3;
            float a = g[0], c = g[1], d = g[2];
            pres[k] = !((a != a) || (c != c) || (d != d));
            a = (a != a) ? 0.0f : a;
            c = (c != c) ? 0.0f : c;
            d = (d != d) ? 0.0f : d;
            fs[k] = a; fe[k] = c;
            int ci = (int)d;
            cli[k] = ci < 0 ? 0 : (ci > CC - 1 ? CC - 1 : ci);
        }
        bool rowdone[KK];
        for (int k = 0; k < KK; k++) rowdone[k] = false;
        int used[KK]; int nused = 0;

        for (int it = 0; it < KK; it++) {
            float bvv = FLT_MAX; int bk = -1, bcol = -1;
            for (int k = 0; k < KK; k++) {             // ascending row: flat-index tie-break
                if (!pres[k] || rowdone[k]) continue;
                for (int j = 0; j < KK; j++) {          // list sorted by (val, col)
                    int col = g_cand_col[(b * KK + k) * KK + j];
                    bool isused = false;
                    for (int u = 0; u < nused; u++) isused |= (used[u] == col);
                    if (isused) continue;
                    float v = g_cand_val[(b * KK + k) * KK + j];
                    if (v < bvv) { bvv = v; bk = k; bcol = col; }
                    break;                              // first unmasked = row min
                }
            }
            if (bk < 0) break;                          // only absent rows remain -> invalid picks, zero loss
            rowdone[bk] = true; used[nused++] = bcol;
            if (bvv < 0.5e6f) {                         // valid = val < VL/2
                m += 1.0f;
                size_t idx = (size_t)b * NN + bcol;
                float ss = sigmoidf_(ps[idx]);
                float se = sigmoidf_(pe[idx]);
                float gs = fs[bk], ge = fe[bk];
                float dls = ss - gs, dle = se - ge;
                part += dls * dls + dle * dle;          // loc
                float l0 = pcl[idx * 2], l1 = pcl[idx * 2 + 1];
                float bce = (cli[bk] == 0) ? (softplusf_(-l0) + softplusf_(l1))
                                           : (softplusf_(l0) + softplusf_(-l1));
                part += bce;                            // class
                float a1 = fminf(ss, se), b1 = fmaxf(ss, se);
                float a2 = fminf(gs, ge), b2 = fmaxf(gs, ge);
                float inter = fmaxf(0.0f, fminf(b1, b2) - fmaxf(a1, a2));
                float uni = fmaxf(1e-8f, fmaxf(b1, b2) - fminf(a1, a2));
                float iou = inter / uni;
                float dcf = sigmoidf_(pcf[idx]) - iou;
                part += dcf * dcf;                      // conf
            }
        }
    }
    __shared__ float sP[64], sM[64];
    sP[threadIdx.x] = part; sM[threadIdx.x] = m;
    __syncthreads();
    for (int st = 32; st > 0; st >>= 1) {
        if (threadIdx.x < st) {
            sP[threadIdx.x] += sP[threadIdx.x + st];
            sM[threadIdx.x] += sM[threadIdx.x + st];
        }
        __syncthreads();
    }
    if (threadIdx.x == 0) {
        float M = sM[0];
        out[0] = (M > 0.0f) ? (sP[0] / (M + 1e-8f)) : 0.0f;
    }
}

// ---------------------------------------------------------------------------
extern "C" void kernel_launch(void* const* d_in, const int* in_sizes, int n_in,
                              void* d_out, int out_size) {
    const float* ps  = (const float*)d_in[0];   // (B, N)
    const float* pe  = (const float*)d_in[1];   // (B, N)
    const float* pcl = (const float*)d_in[2];   // (B, N, 2)
    const float* pcf = (const float*)d_in[3];   // (B, N)
    const float* gt  = (const float*)d_in[4];   // (B, K, 3)
    float* out = (float*)d_out;

    precompute_kernel<<<(BB * NN + 255) / 256, 256>>>(ps, pe, pcl);
    topk_kernel<<<(BB * KK * 32 + 255) / 256, 256>>>(gt);
    match_kernel<<<1, 64>>>(ps, pe, pcl, pcf, gt, out);
}

// round 2
// speedup vs baseline: 1.4794x; 1.4794x over previous
#include <cuda_runtime.h>
#include <math.h>
#include <float.h>

#define BB 64
#define NN 32768
#define CC 2
#define KK 10
#define SS 16            // segments per batch row
#define SEG (NN / SS)    // 2048 columns per segment

static __device__ __forceinline__ float sigmoidf_(float x) {
    return 1.0f / (1.0f + expf(-x));
}
static __device__ __forceinline__ float softplusf_(float x) {
    return fmaxf(x, 0.0f) + log1pf(expf(-fabsf(x)));
}

// partial top-10 per (batch, row, segment)
__device__ float g_part_val[BB * KK * SS * KK];
__device__ int   g_part_col[BB * KK * SS * KK];
// merged top-10 per (batch, row), sorted by (val, col) ascending
__device__ float g_cand_val[BB * KK * KK];
__device__ int   g_cand_col[BB * KK * KK];

// ---------------------------------------------------------------------------
// Kernel A: fused feature compute + per-segment top-10.
// One block per (batch, segment). 512 threads: all compute features into smem,
// warps 0..9 then scan the tile for their GT row.
// ---------------------------------------------------------------------------
__global__ __launch_bounds__(512) void fused_topk_kernel(
        const float* __restrict__ ps,
        const float* __restrict__ pe,
        const float* __restrict__ pcl,
        const float* __restrict__ gt) {
    __shared__ float4 feat[SEG];  // 32KB: (s, e, g0, g1)

    int b = blockIdx.x / SS;
    int seg = blockIdx.x % SS;
    int base = seg * SEG;
    size_t gbase = (size_t)b * NN + base;

    // ---- feature phase: 512 threads x 4 columns ----
    const float2* pcl2 = reinterpret_cast<const float2*>(pcl);
    for (int i = threadIdx.x; i < SEG; i += 512) {
        float s = sigmoidf_(ps[gbase + i]);
        float e = sigmoidf_(pe[gbase + i]);
        float2 l = pcl2[gbase + i];
        float c0 = sigmoidf_(l.x);
        float c1 = sigmoidf_(l.y);
        float g0 = (c0 - 1.0f) * (c0 - 1.0f) + c1 * c1;
        float g1 = c0 * c0 + (c1 - 1.0f) * (c1 - 1.0f);
        feat[i] = make_float4(s, e, g0, g1);
    }
    __syncthreads();

    int w = threadIdx.x >> 5;
    int lane = threadIdx.x & 31;
    if (w >= KK) return;

    int obase = ((b * KK + w) * SS + seg) * KK;

    const float* g = gt + (size_t)(b * KK + w) * 3;
    float fs = g[0], fe = g[1], cl = g[2];
    bool present = !((fs != fs) || (fe != fe) || (cl != cl));
    if (!present) {
        // deterministic sentinels; match kernel skips absent rows anyway
        if (lane < KK) { g_part_val[obase + lane] = 1.0e6f; g_part_col[obase + lane] = base + lane; }
        return;
    }
    int cli = (int)cl;
    cli = cli < 0 ? 0 : (cli > CC - 1 ? CC - 1 : cli);

    // per-lane sorted top-10 (ascending (val, col)); ascending col iteration +
    // strict-less insert preserves smallest-col on value ties
    float bv[KK]; int bc[KK];
#pragma unroll
    for (int j = 0; j < KK; j++) { bv[j] = FLT_MAX; bc[j] = 0x7fffffff; }

    for (int i = lane; i < SEG; i += 32) {
        float4 v = feat[i];
        float gg = (cli == 0) ? v.z : v.w;
        float ds = v.x - fs, de = v.y - fe;
        float cost = fmaf(ds, ds, fmaf(de, de, gg));
        if (cost < bv[KK - 1]) {
            bv[KK - 1] = cost; bc[KK - 1] = base + i;
#pragma unroll
            for (int j = KK - 1; j > 0; j--) {
                bool sw = (bv[j] < bv[j - 1]);
                if (sw) {
                    float tv = bv[j]; bv[j] = bv[j - 1]; bv[j - 1] = tv;
                    int tc = bc[j]; bc[j] = bc[j - 1]; bc[j - 1] = tc;
                }
            }
        }
    }

    // warp merge: 10 rounds of butterfly-min over each lane's list head
    int p = 0;
    for (int r = 0; r < KK; r++) {
        float v = FLT_MAX; int c = 0x7fffffff;
#pragma unroll
        for (int j = KK - 1; j >= 0; j--) {
            if (j >= p) { v = bv[j]; c = bc[j]; }
        }
        int src = lane;
#pragma unroll
        for (int off = 16; off > 0; off >>= 1) {
            float v2 = __shfl_xor_sync(0xffffffffu, v, off);
            int   c2 = __shfl_xor_sync(0xffffffffu, c, off);
            int   s2 = __shfl_xor_sync(0xffffffffu, src, off);
            if (v2 < v || (v2 == v && c2 < c)) { v = v2; c = c2; src = s2; }
        }
        if (lane == 0) { g_part_val[obase + r] = v; g_part_col[obase + r] = c; }
        if (lane == src) p++;
    }
}

// ---------------------------------------------------------------------------
// Kernel B: merge SS*KK = 160 partial candidates -> global top-10 per (b,k).
// One warp per (b,k); 5 candidates per lane.
// ---------------------------------------------------------------------------
__global__ void merge_kernel() {
    int warp = (blockIdx.x * blockDim.x + threadIdx.x) >> 5;
    int lane = threadIdx.x & 31;
    if (warp >= BB * KK) return;
    int ibase = warp * (SS * KK);   // 160 entries

    float lv[5]; int lc[5];
#pragma unroll
    for (int j = 0; j < 5; j++) {
        int idx = j * 32 + lane;
        lv[j] = g_part_val[ibase + idx];
        lc[j] = g_part_col[ibase + idx];
    }
    // sort 5 by (val, col) ascending — insertion sort
#pragma unroll
    for (int a = 1; a < 5; a++) {
#pragma unroll
        for (int j = a; j > 0; j--) {
            bool sw = (lv[j] < lv[j - 1]) || (lv[j] == lv[j - 1] && lc[j] < lc[j - 1]);
            if (sw) {
                float tv = lv[j]; lv[j] = lv[j - 1]; lv[j - 1] = tv;
                int tc = lc[j]; lc[j] = lc[j - 1]; lc[j - 1] = tc;
            }
        }
    }

    int p = 0;
    for (int r = 0; r < KK; r++) {
        float v = FLT_MAX; int c = 0x7fffffff;
#pragma unroll
        for (int j = 4; j >= 0; j--) {
            if (j >= p) { v = lv[j]; c = lc[j]; }
        }
        int src = lane;
#pragma unroll
        for (int off = 16; off > 0; off >>= 1) {
            float v2 = __shfl_xor_sync(0xffffffffu, v, off);
            int   c2 = __shfl_xor_sync(0xffffffffu, c, off);
            int   s2 = __shfl_xor_sync(0xffffffffu, src, off);
            if (v2 < v || (v2 == v && c2 < c)) { v = v2; c = c2; src = s2; }
        }
        if (lane == 0) { g_cand_val[warp * KK + r] = v; g_cand_col[warp * KK + r] = c; }
        if (lane == src) p++;
    }
}

// ---------------------------------------------------------------------------
// Kernel C: greedy match on candidate lists + exact losses + final scalar
// ---------------------------------------------------------------------------
__global__ void match_kernel(const float* __restrict__ ps,
                             const float* __restrict__ pe,
                             const float* __restrict__ pcl,
                             const float* __restrict__ pcf,
                             const float* __restrict__ gt,
                             float* __restrict__ out) {
    int b = threadIdx.x;
    float part = 0.0f, m = 0.0f;
    if (b < BB) {
        float fs[KK], fe[KK]; int cli[KK]; bool pres[KK];
        for (int k = 0; k < KK; k++) {
            const float* g = gt + (size_t)(b * KK + k) * 3;
            float a = g[0], c = g[1], d = g[2];
            pres[k] = !((a != a) || (c != c) || (d != d));
            a = (a != a) ? 0.0f : a;
            c = (c != c) ? 0.0f : c;
            d = (d != d) ? 0.0f : d;
            fs[k] = a; fe[k] = c;
            int ci = (int)d;
            cli[k] = ci < 0 ? 0 : (ci > CC - 1 ? CC - 1 : ci);
        }
        bool rowdone[KK];
        for (int k = 0; k < KK; k++) rowdone[k] = false;
        int used[KK]; int nused = 0;

        for (int it = 0; it < KK; it++) {
            float bvv = FLT_MAX; int bk = -1, bcol = -1;
            for (int k = 0; k < KK; k++) {              // ascending row: flat-index tie-break
                if (!pres[k] || rowdone[k]) continue;
                for (int j = 0; j < KK; j++) {          // list sorted by (val, col)
                    int col = g_cand_col[(b * KK + k) * KK + j];
                    bool isused = false;
                    for (int u = 0; u < nused; u++) isused |= (used[u] == col);
                    if (isused) continue;
                    float v = g_cand_val[(b * KK + k) * KK + j];
                    if (v < bvv) { bvv = v; bk = k; bcol = col; }
                    break;                              // first unmasked = row min
                }
            }
            if (bk < 0) break;
            rowdone[bk] = true; used[nused++] = bcol;
            if (bvv < 0.5e6f) {                         // valid = val < VL/2
                m += 1.0f;
                size_t idx = (size_t)b * NN + bcol;
                float ss = sigmoidf_(ps[idx]);
                float se = sigmoidf_(pe[idx]);
                float gs = fs[bk], ge = fe[bk];
                float dls = ss - gs, dle = se - ge;
                part += dls * dls + dle * dle;          // loc
                float l0 = pcl[idx * 2], l1 = pcl[idx * 2 + 1];
                float bce = (cli[bk] == 0) ? (softplusf_(-l0) + softplusf_(l1))
                                           : (softplusf_(l0) + softplusf_(-l1));
                part += bce;                            // class
                float a1 = fminf(ss, se), b1 = fmaxf(ss, se);
                float a2 = fminf(gs, ge), b2 = fmaxf(gs, ge);
                float inter = fmaxf(0.0f, fminf(b1, b2) - fmaxf(a1, a2));
                float uni = fmaxf(1e-8f, fmaxf(b1, b2) - fminf(a1, a2));
                float iou = inter / uni;
                float dcf = sigmoidf_(pcf[idx]) - iou;
                part += dcf * dcf;                      // conf
            }
        }
    }
    __shared__ float sP[64], sM[64];
    sP[threadIdx.x] = part; sM[threadIdx.x] = m;
    __syncthreads();
    for (int st = 32; st > 0; st >>= 1) {
        if (threadIdx.x < st) {
            sP[threadIdx.x] += sP[threadIdx.x + st];
            sM[threadIdx.x] += sM[threadIdx.x + st];
        }
        __syncthreads();
    }
    if (threadIdx.x == 0) {
        float M = sM[0];
        out[0] = (M > 0.0f) ? (sP[0] / (M + 1e-8f)) : 0.0f;
    }
}

// ---------------------------------------------------------------------------
extern "C" void kernel_launch(void* const* d_in, const int* in_sizes, int n_in,
                              void* d_out, int out_size) {
    const float* ps  = (const float*)d_in[0];   // (B, N)
    const float* pe  = (const float*)d_in[1];   // (B, N)
    const float* pcl = (const float*)d_in[2];   // (B, N, 2)
    const float* pcf = (const float*)d_in[3];   // (B, N)
    const float* gt  = (const float*)d_in[4];   // (B, K, 3)
    float* out = (float*)d_out;

    fused_topk_kernel<<<BB * SS, 512>>>(ps, pe, pcl, gt);
    merge_kernel<<<(BB * KK * 32 + 255) / 256, 256>>>();
    match_kernel<<<1, 64>>>(ps, pe, pcl, pcf, gt, out);
}

// round 3
// speedup vs baseline: 2.7449x; 1.8554x over previous
#include <cuda_runtime.h>
#include <math.h>
#include <float.h>

#define BB 64
#define NN 32768
#define CC 2
#define KK 10
#define QT 4              // quarters per batch row (one block each)
#define TPQ 4             // smem tiles per quarter
#define SEG 2048          // columns per tile
#define FULLM 0xffffffffu

static __device__ __forceinline__ float sigmoidf_(float x) {
    return 1.0f / (1.0f + expf(-x));
}
static __device__ __forceinline__ float softplusf_(float x) {
    return fmaxf(x, 0.0f) + log1pf(expf(-fabsf(x)));
}

// partial top-10 per (batch, row, quarter)
__device__ float g_part_val[BB * KK * QT * KK];
__device__ int   g_part_col[BB * KK * QT * KK];
// per-batch loss partials
__device__ float g_bpart[BB];
__device__ float g_bm[BB];

// ---------------------------------------------------------------------------
// Kernel A: fused features + warp-collective top-10 per (batch, row, quarter)
// Block = (batch, quarter). 512 threads. Warps 0..9 own GT rows 0..9.
// ---------------------------------------------------------------------------
__global__ __launch_bounds__(512) void fused_topk_kernel(
        const float* __restrict__ ps,
        const float* __restrict__ pe,
        const float* __restrict__ pcl,
        const float* __restrict__ gt) {
    __shared__ float4 feat[SEG];  // 32KB: (s, e, h0, h1)

    int b = blockIdx.x / QT;
    int qtr = blockIdx.x % QT;
    int qbase = qtr * (TPQ * SEG);

    int w = threadIdx.x >> 5;
    int lane = threadIdx.x & 31;

    // row constants for scan warps
    float fs = 0.0f, fe = 0.0f, ms = 0.0f, me = 0.0f;
    int cli = 0;
    bool present = false;
    if (w < KK) {
        const float* g = gt + (size_t)(b * KK + w) * 3;
        fs = g[0]; fe = g[1];
        float cl = g[2];
        present = !((fs != fs) || (fe != fe) || (cl != cl));
        if (present) {
            int ci = (int)cl;
            cli = ci < 0 ? 0 : (ci > CC - 1 ? CC - 1 : ci);
            ms = -2.0f * fs;
            me = -2.0f * fe;
        }
    }

    // distributed top-10: lane j (<10) holds the j-th best (val', col)
    float lv = FLT_MAX;
    int lc = 0x7fffffff;
    float tau = FLT_MAX;

    const float2* pcl2 = reinterpret_cast<const float2*>(pcl);

    for (int t = 0; t < TPQ; t++) {
        int colbase = qbase + t * SEG;
        size_t gbase = (size_t)b * NN + colbase;

        // ---- feature phase: all 512 threads ----
        for (int i = threadIdx.x; i < SEG; i += 512) {
            float s = sigmoidf_(ps[gbase + i]);
            float e = sigmoidf_(pe[gbase + i]);
            float2 l = pcl2[gbase + i];
            float c0 = sigmoidf_(l.x);
            float c1 = sigmoidf_(l.y);
            float base = fmaf(s, s, fmaf(e, e, fmaf(c0, c0, fmaf(c1, c1, 1.0f))));
            feat[i] = make_float4(s, e, base - 2.0f * c0, base - 2.0f * c1);
        }
        __syncthreads();

        // ---- scan phase: warps 0..9 ----
        if (w < KK && present) {
            for (int r = 0; r < SEG / 32; r++) {
                int i = r * 32 + lane;
                float4 f = feat[i];
                float h = (cli == 0) ? f.z : f.w;
                float v = fmaf(f.x, ms, fmaf(f.y, me, h));
                int gcol = colbase + i;
                unsigned bal = __ballot_sync(FULLM, v <= tau);
                while (bal) {
                    int src = __ffs(bal) - 1;
                    bal &= bal - 1;
                    float bv = __shfl_sync(FULLM, v, src);
                    int   bc = __shfl_sync(FULLM, gcol, src);
                    if (!(bv <= tau)) continue;   // stale after earlier insert
                    bool less = (lv < bv) || (lv == bv && lc < bc);
                    unsigned lm = __ballot_sync(FULLM, less) & 0x3FFu;
                    int pos = __popc(lm);
                    float upv = __shfl_up_sync(FULLM, lv, 1);
                    int   upc = __shfl_up_sync(FULLM, lc, 1);
                    if (pos < KK && lane < KK) {
                        if (lane == pos) { lv = bv; lc = bc; }
                        else if (lane > pos) { lv = upv; lc = upc; }
                    }
                    tau = __shfl_sync(FULLM, lv, KK - 1);
                }
            }
        }
        __syncthreads();
    }

    // ---- write partials ----
    if (w < KK && lane < KK) {
        int obase = ((b * KK + w) * QT + qtr) * KK;
        if (present) {
            float ck = fmaf(fs, fs, fe * fe);   // add back row constant
            g_part_val[obase + lane] = lv + ck;
            g_part_col[obase + lane] = lc;
        } else {
            g_part_val[obase + lane] = 1.0e6f;  // sentinel; never selected as valid
            g_part_col[obase + lane] = qbase + lane;
        }
    }
}

// ---------------------------------------------------------------------------
// Kernel B: per-batch merge (10 warps, one per row) + greedy match + losses
// ---------------------------------------------------------------------------
__global__ __launch_bounds__(320) void merge_match_kernel(
        const float* __restrict__ ps,
        const float* __restrict__ pe,
        const float* __restrict__ pcl,
        const float* __restrict__ pcf,
        const float* __restrict__ gt) {
    __shared__ float sval[KK * KK];
    __shared__ int   scol[KK * KK];
    __shared__ float s_fs[KK], s_fe[KK];
    __shared__ int   s_cli[KK];
    __shared__ int   s_mk[KK], s_mcol[KK];
    __shared__ int   s_nm;
    __shared__ float s_loss[KK];

    int b = blockIdx.x;
    int w = threadIdx.x >> 5;
    int lane = threadIdx.x & 31;

    // ---- merge 40 partials -> top-10 per row ----
    if (w < KK) {
        int ibase = (b * KK + w) * (QT * KK);   // 40 entries
        float lv0 = g_part_val[ibase + lane];
        int   lc0 = g_part_col[ibase + lane];
        float lv1 = FLT_MAX;
        int   lc1 = 0x7fffffff;
        if (lane < QT * KK - 32) {
            lv1 = g_part_val[ibase + 32 + lane];
            lc1 = g_part_col[ibase + 32 + lane];
        }
        if (lv1 < lv0 || (lv1 == lv0 && lc1 < lc0)) {
            float tv = lv0; lv0 = lv1; lv1 = tv;
            int tc = lc0; lc0 = lc1; lc1 = tc;
        }
        int p = 0;
        for (int r = 0; r < KK; r++) {
            float v = FLT_MAX; int c = 0x7fffffff;
            if (p == 1) { v = lv1; c = lc1; }
            if (p == 0) { v = lv0; c = lc0; }
            int src = lane;
#pragma unroll
            for (int off = 16; off > 0; off >>= 1) {
                float v2 = __shfl_xor_sync(FULLM, v, off);
                int   c2 = __shfl_xor_sync(FULLM, c, off);
                int   s2 = __shfl_xor_sync(FULLM, src, off);
                if (v2 < v || (v2 == v && c2 < c)) { v = v2; c = c2; src = s2; }
            }
            if (lane == 0) { sval[w * KK + r] = v; scol[w * KK + r] = c; }
            if (lane == src) p++;
        }
    }
    // GT row constants (threads 0..9)
    if (threadIdx.x < KK) {
        const float* g = gt + (size_t)(b * KK + threadIdx.x) * 3;
        float a = g[0], c = g[1], d = g[2];
        bool pres = !((a != a) || (c != c) || (d != d));
        s_fs[threadIdx.x] = (a != a) ? 0.0f : a;
        s_fe[threadIdx.x] = (c != c) ? 0.0f : c;
        d = (d != d) ? 0.0f : d;
        int ci = (int)d;
        ci = ci < 0 ? 0 : (ci > CC - 1 ? CC - 1 : ci);
        s_cli[threadIdx.x] = pres ? ci : -1;   // -1 marks absent
    }
    __syncthreads();

    // ---- greedy match (thread 0, all data in smem) ----
    if (threadIdx.x == 0) {
        bool rowdone[KK];
        int used[KK]; int nused = 0;
        int nm = 0;
#pragma unroll
        for (int k = 0; k < KK; k++) rowdone[k] = false;

        for (int it = 0; it < KK; it++) {
            float bvv = FLT_MAX; int bk = -1, bcol = -1;
            for (int k = 0; k < KK; k++) {              // ascending row = flat-idx tie-break
                if (s_cli[k] < 0 || rowdone[k]) continue;
                for (int j = 0; j < KK; j++) {          // sorted by (val, col)
                    int col = scol[k * KK + j];
                    bool isused = false;
                    for (int u = 0; u < nused; u++) isused |= (used[u] == col);
                    if (isused) continue;
                    float v = sval[k * KK + j];
                    if (v < bvv) { bvv = v; bk = k; bcol = col; }
                    break;                               // first unmasked = row min
                }
            }
            if (bk < 0) break;
            rowdone[bk] = true; used[nused++] = bcol;
            if (bvv < 0.5e6f) { s_mk[nm] = bk; s_mcol[nm] = bcol; nm++; }
        }
        s_nm = nm;
    }
    __syncthreads();

    // ---- loss terms in parallel (threads 0..nm-1) ----
    int nm = s_nm;
    if (threadIdx.x < KK) {
        float part = 0.0f;
        if (threadIdx.x < nm) {
            int k = s_mk[threadIdx.x];
            int col = s_mcol[threadIdx.x];
            size_t idx = (size_t)b * NN + col;
            float ss = sigmoidf_(ps[idx]);
            float se = sigmoidf_(pe[idx]);
            float gs = s_fs[k], ge = s_fe[k];
            float dls = ss - gs, dle = se - ge;
            part = dls * dls + dle * dle;               // loc
            float l0 = pcl[idx * 2], l1 = pcl[idx * 2 + 1];
            part += (s_cli[k] == 0) ? (softplusf_(-l0) + softplusf_(l1))
                                    : (softplusf_(l0) + softplusf_(-l1));   // class
            float a1 = fminf(ss, se), b1 = fmaxf(ss, se);
            float a2 = fminf(gs, ge), b2 = fmaxf(gs, ge);
            float inter = fmaxf(0.0f, fminf(b1, b2) - fmaxf(a1, a2));
            float uni = fmaxf(1e-8f, fmaxf(b1, b2) - fminf(a1, a2));
            float iou = inter / uni;
            float dcf = sigmoidf_(pcf[idx]) - iou;
            part += dcf * dcf;                          // conf
        }
        s_loss[threadIdx.x < nm ? threadIdx.x : 0] = 0.0f;  // ensure init
    }
    __syncthreads();
    if (threadIdx.x < KK) {
        if (threadIdx.x < nm) {
            int k = s_mk[threadIdx.x];
            int col = s_mcol[threadIdx.x];
            size_t idx = (size_t)b * NN + col;
            float ss = sigmoidf_(ps[idx]);
            float se = sigmoidf_(pe[idx]);
            float gs = s_fs[k], ge = s_fe[k];
            float dls = ss - gs, dle = se - ge;
            float part = dls * dls + dle * dle;
            float l0 = pcl[idx * 2], l1 = pcl[idx * 2 + 1];
            part += (s_cli[k] == 0) ? (softplusf_(-l0) + softplusf_(l1))
                                    : (softplusf_(l0) + softplusf_(-l1));
            float a1 = fminf(ss, se), b1 = fmaxf(ss, se);
            float a2 = fminf(gs, ge), b2 = fmaxf(gs, ge);
            float inter = fmaxf(0.0f, fminf(b1, b2) - fmaxf(a1, a2));
            float uni = fmaxf(1e-8f, fmaxf(b1, b2) - fminf(a1, a2));
            float iou = inter / uni;
            float dcf = sigmoidf_(pcf[idx]) - iou;
            part += dcf * dcf;
            s_loss[threadIdx.x] = part;
        } else {
            s_loss[threadIdx.x] = 0.0f;
        }
    }
    __syncthreads();
    if (threadIdx.x == 0) {
        float tot = 0.0f;
#pragma unroll
        for (int j = 0; j < KK; j++) tot += s_loss[j];
        g_bpart[b] = tot;
        g_bm[b] = (float)nm;
    }
}

// ---------------------------------------------------------------------------
// Kernel C: final reduction over batches
// ---------------------------------------------------------------------------
__global__ void finalize_kernel(float* __restrict__ out) {
    __shared__ float sP[BB], sM[BB];
    sP[threadIdx.x] = g_bpart[threadIdx.x];
    sM[threadIdx.x] = g_bm[threadIdx.x];
    __syncthreads();
    for (int st = 32; st > 0; st >>= 1) {
        if (threadIdx.x < st) {
            sP[threadIdx.x] += sP[threadIdx.x + st];
            sM[threadIdx.x] += sM[threadIdx.x + st];
        }
        __syncthreads();
    }
    if (threadIdx.x == 0) {
        float M = sM[0];
        out[0] = (M > 0.0f) ? (sP[0] / (M + 1e-8f)) : 0.0f;
    }
}

// ---------------------------------------------------------------------------
extern "C" void kernel_launch(void* const* d_in, const int* in_sizes, int n_in,
                              void* d_out, int out_size) {
    const float* ps  = (const float*)d_in[0];   // (B, N)
    const float* pe  = (const float*)d_in[1];   // (B, N)
    const float* pcl = (const float*)d_in[2];   // (B, N, 2)
    const float* pcf = (const float*)d_in[3];   // (B, N)
    const float* gt  = (const float*)d_in[4];   // (B, K, 3)
    float* out = (float*)d_out;

    fused_topk_kernel<<<BB * QT, 512>>>(ps, pe, pcl, gt);
    merge_match_kernel<<<BB, 320>>>(ps, pe, pcl, pcf, gt);
    finalize_kernel<<<1, BB>>>(out);
}